// round 4
// baseline (speedup 1.0000x reference)
#include <cuda_runtime.h>
#include <math.h>

#define N_NODES 50000
#define N_EDGES 800000

// ---------------- scratch (__device__ globals; float4-typed for alignment) ----------------
__device__ int    g_idx64;                        // 1 if edge_index is int64, 0 if int32
__device__ int    g_deg[N_NODES];
__device__ float  g_invdeg[N_NODES];
__device__ int    g_rowptr[N_NODES + 1];
__device__ int    g_cursor[N_NODES];
__device__ int    g_src[N_EDGES];
__device__ float4 g_agg4[(size_t)N_NODES * 32];   // up to 128 ch per node
__device__ float4 g_ha4 [(size_t)N_NODES * 32];
__device__ float4 g_hb4 [(size_t)N_NODES * 32];

// ---------------- edge-index dtype detection (graph-capture-safe, deterministic) -------
// int64 edge values are < 50000 and non-negative -> every odd 32-bit word is 0.
// For int32 data the odd words are indices (P[all 1024 are 0] ~ (2e-5)^1024 = 0).
__global__ void k_detect(const unsigned int* __restrict__ w) {
    if (blockIdx.x == 0 && threadIdx.x == 0) {
        int is64 = 1;
        for (int i = 1; i < 2048; i += 2)
            if (w[i] != 0u) { is64 = 0; break; }
        g_idx64 = is64;
    }
}

__device__ __forceinline__ int clampi(int v, int lo, int hi) {
    return v < lo ? lo : (v > hi ? hi : v);
}
__device__ __forceinline__ int edge_at(const void* ei, long long pos) {
    int v;
    if (g_idx64) v = (int)((const long long*)ei)[pos];
    else         v = ((const int*)ei)[pos];
    return clampi(v, 0, N_NODES - 1);
}

// ---------------- CSR build ----------------
__global__ void k_zero_deg() {
    int i = blockIdx.x * blockDim.x + threadIdx.x;
    if (i < N_NODES) g_deg[i] = 0;
}

__global__ void k_count(const void* __restrict__ ei) {
    int e = blockIdx.x * blockDim.x + threadIdx.x;
    if (e < N_EDGES) {
        int d = edge_at(ei, (long long)N_EDGES + e);
        atomicAdd(&g_deg[d], 1);
    }
}

// single-block inclusive scan: 1024 threads, ~49-element chunks
__global__ void k_scan() {
    __shared__ int part[1024];
    const int t  = threadIdx.x;
    const int CH = (N_NODES + 1023) / 1024;
    int start = t * CH;
    int end   = start + CH; if (end > N_NODES) end = N_NODES;
    int s = 0;
    for (int i = start; i < end; i++) s += g_deg[i];
    part[t] = s;
    __syncthreads();
    for (int off = 1; off < 1024; off <<= 1) {
        int v = (t >= off) ? part[t - off] : 0;
        __syncthreads();
        if (t >= off) part[t] += v;
        __syncthreads();
    }
    int base = (t == 0) ? 0 : part[t - 1];
    for (int i = start; i < end; i++) {
        int d = g_deg[i];
        g_rowptr[i] = base;
        g_cursor[i] = base;
        g_invdeg[i] = 1.0f / fmaxf((float)d, 1.0f);
        base += d;
    }
    if (t == 1023) g_rowptr[N_NODES] = base;
}

__global__ void k_fill(const void* __restrict__ ei) {
    int e = blockIdx.x * blockDim.x + threadIdx.x;
    if (e < N_EDGES) {
        int s = edge_at(ei, e);
        int d = edge_at(ei, (long long)N_EDGES + e);
        int pos = atomicAdd(&g_cursor[d], 1);
        pos = clampi(pos, 0, N_EDGES - 1);
        g_src[pos] = s;
    }
}

// ---------------- atomic-free mean aggregation: one warp per node ----------------
// SSEL: 0 = xparam (harness input), 1 = g_ha4, 2 = g_hb4. Output: g_agg4.
template <int C, int SSEL>
__global__ void k_agg(const float4* __restrict__ xparam4) {
    const float4* feat = (SSEL == 0) ? xparam4 : (SSEL == 1) ? (const float4*)g_ha4
                                                             : (const float4*)g_hb4;
    int w    = (blockIdx.x * blockDim.x + threadIdx.x) >> 5;
    int lane = threadIdx.x & 31;
    if (w >= N_NODES) return;
    int beg = g_rowptr[w], end = g_rowptr[w + 1];
    if (C == 128) {
        float4 a = make_float4(0.f, 0.f, 0.f, 0.f);
        int e = beg;
        for (; e + 1 < end; e += 2) {
            int s0 = g_src[e];
            int s1 = g_src[e + 1];
            float4 v0 = feat[(size_t)s0 * 32 + lane];
            float4 v1 = feat[(size_t)s1 * 32 + lane];
            a.x += v0.x; a.y += v0.y; a.z += v0.z; a.w += v0.w;
            a.x += v1.x; a.y += v1.y; a.z += v1.z; a.w += v1.w;
        }
        if (e < end) {
            int s0 = g_src[e];
            float4 v0 = feat[(size_t)s0 * 32 + lane];
            a.x += v0.x; a.y += v0.y; a.z += v0.z; a.w += v0.w;
        }
        float iv = g_invdeg[w];
        a.x *= iv; a.y *= iv; a.z *= iv; a.w *= iv;
        g_agg4[(size_t)w * 32 + lane] = a;
    } else { // C == 64 : rows are 32 float2 wide
        const float2* f2 = (const float2*)feat;
        float2 a = make_float2(0.f, 0.f);
        int e = beg;
        for (; e + 1 < end; e += 2) {
            int s0 = g_src[e];
            int s1 = g_src[e + 1];
            float2 v0 = f2[(size_t)s0 * 32 + lane];
            float2 v1 = f2[(size_t)s1 * 32 + lane];
            a.x += v0.x; a.y += v0.y;
            a.x += v1.x; a.y += v1.y;
        }
        if (e < end) {
            int s0 = g_src[e];
            float2 v0 = f2[(size_t)s0 * 32 + lane];
            a.x += v0.x; a.y += v0.y;
        }
        float iv = g_invdeg[w];
        a.x *= iv; a.y *= iv;
        ((float2*)g_agg4)[(size_t)w * 32 + lane] = a;
    }
}

// ---------------- fused SAGE GEMM: out = mean@Wl^T + bl + x@Wr^T (+relu / +log_softmax) ------
// 256 threads/block, one BM-node tile per block, K processed in KC=16 chunks.
// Static shared only. Thread owns R=8 rows x 4 output channels.
// XSEL: 0 = xparam, 1 = g_ha4, 2 = g_hb4.   OSEL: 0 = outparam, 1 = g_ha4, 2 = g_hb4.
template <int CIN, int COUT, int BM, bool RELU, bool LSM, int XSEL, int OSEL>
__launch_bounds__(256, 1)
__global__ void k_gemm(const float4* __restrict__ xparam4,
                       const float* __restrict__ Wl, const float* __restrict__ bl,
                       const float* __restrict__ Wr, float* __restrict__ outparam) {
    constexpr int KC    = 16;                 // K-chunk (in floats)
    constexpr int KQ    = KC / 4;             // K-chunk in float4
    constexpr int NCG   = COUT / 4;           // channel groups
    constexpr int NGR   = 256 / NCG;          // node groups
    constexpr int R     = BM / NGR;           // rows per thread (== 8)
    constexpr int COUTP = COUT + 4;           // pad
    constexpr int C4    = CIN / 4;

    __shared__ float  Wl_s[KC][COUTP];
    __shared__ float  Wr_s[KC][COUTP];
    __shared__ float4 vm4[BM][KQ];
    __shared__ float4 vx4[BM][KQ];

    const float4* xin4  = (XSEL == 0) ? xparam4 : (XSEL == 1) ? (const float4*)g_ha4
                                                              : (const float4*)g_hb4;
    const float4* mean4 = (const float4*)g_agg4;
    float*        out   = (OSEL == 0) ? outparam : (OSEL == 1) ? (float*)g_ha4
                                                               : (float*)g_hb4;

    const int tid = threadIdx.x;
    const int cg  = tid % NCG;
    const int ng  = tid / NCG;
    const int nb  = blockIdx.x * BM;

    float acc[R][4];
    {
        float b0 = bl[cg * 4 + 0], b1 = bl[cg * 4 + 1];
        float b2 = bl[cg * 4 + 2], b3 = bl[cg * 4 + 3];
        #pragma unroll
        for (int r = 0; r < R; r++) {
            acc[r][0] = b0; acc[r][1] = b1; acc[r][2] = b2; acc[r][3] = b3;
        }
    }

    for (int kb4 = 0; kb4 < C4; kb4 += KQ) {
        __syncthreads();
        // stage weight K-panels: Wl/Wr are [co][ci] row-major; smem is [k][co]
        for (int idx = tid; idx < KC * COUT; idx += 256) {
            int co = idx / KC;
            int k  = idx % KC;
            Wl_s[k][co] = Wl[co * CIN + kb4 * 4 + k];
            Wr_s[k][co] = Wr[co * CIN + kb4 * 4 + k];
        }
        // stage value tiles (float4, coalesced)
        for (int idx = tid; idx < BM * KQ; idx += 256) {
            int nl = idx / KQ;
            int q  = idx % KQ;
            int n  = nb + nl; if (n >= N_NODES) n = N_NODES - 1;
            vm4[nl][q] = mean4[(size_t)n * C4 + kb4 + q];
            vx4[nl][q] = xin4 [(size_t)n * C4 + kb4 + q];
        }
        __syncthreads();

        #pragma unroll
        for (int q = 0; q < KQ; q++) {
            float4 wl[4], wr[4];
            #pragma unroll
            for (int j = 0; j < 4; j++) {
                wl[j] = *(const float4*)&Wl_s[q * 4 + j][cg * 4];
                wr[j] = *(const float4*)&Wr_s[q * 4 + j][cg * 4];
            }
            #pragma unroll
            for (int r = 0; r < R; r++) {
                float4 m = vm4[ng * R + r][q];
                float4 x = vx4[ng * R + r][q];
                acc[r][0] = fmaf(m.x, wl[0].x, acc[r][0]);
                acc[r][1] = fmaf(m.x, wl[0].y, acc[r][1]);
                acc[r][2] = fmaf(m.x, wl[0].z, acc[r][2]);
                acc[r][3] = fmaf(m.x, wl[0].w, acc[r][3]);
                acc[r][0] = fmaf(x.x, wr[0].x, acc[r][0]);
                acc[r][1] = fmaf(x.x, wr[0].y, acc[r][1]);
                acc[r][2] = fmaf(x.x, wr[0].z, acc[r][2]);
                acc[r][3] = fmaf(x.x, wr[0].w, acc[r][3]);

                acc[r][0] = fmaf(m.y, wl[1].x, acc[r][0]);
                acc[r][1] = fmaf(m.y, wl[1].y, acc[r][1]);
                acc[r][2] = fmaf(m.y, wl[1].z, acc[r][2]);
                acc[r][3] = fmaf(m.y, wl[1].w, acc[r][3]);
                acc[r][0] = fmaf(x.y, wr[1].x, acc[r][0]);
                acc[r][1] = fmaf(x.y, wr[1].y, acc[r][1]);
                acc[r][2] = fmaf(x.y, wr[1].z, acc[r][2]);
                acc[r][3] = fmaf(x.y, wr[1].w, acc[r][3]);

                acc[r][0] = fmaf(m.z, wl[2].x, acc[r][0]);
                acc[r][1] = fmaf(m.z, wl[2].y, acc[r][1]);
                acc[r][2] = fmaf(m.z, wl[2].z, acc[r][2]);
                acc[r][3] = fmaf(m.z, wl[2].w, acc[r][3]);
                acc[r][0] = fmaf(x.z, wr[2].x, acc[r][0]);
                acc[r][1] = fmaf(x.z, wr[2].y, acc[r][1]);
                acc[r][2] = fmaf(x.z, wr[2].z, acc[r][2]);
                acc[r][3] = fmaf(x.z, wr[2].w, acc[r][3]);

                acc[r][0] = fmaf(m.w, wl[3].x, acc[r][0]);
                acc[r][1] = fmaf(m.w, wl[3].y, acc[r][1]);
                acc[r][2] = fmaf(m.w, wl[3].z, acc[r][2]);
                acc[r][3] = fmaf(m.w, wl[3].w, acc[r][3]);
                acc[r][0] = fmaf(x.w, wr[3].x, acc[r][0]);
                acc[r][1] = fmaf(x.w, wr[3].y, acc[r][1]);
                acc[r][2] = fmaf(x.w, wr[3].z, acc[r][2]);
                acc[r][3] = fmaf(x.w, wr[3].w, acc[r][3]);
            }
        }
    }

    // epilogue
    #pragma unroll
    for (int r = 0; r < R; r++) {
        int n = nb + ng * R + r;
        float v0 = acc[r][0], v1 = acc[r][1], v2 = acc[r][2], v3 = acc[r][3];
        if (RELU) {
            v0 = fmaxf(v0, 0.f); v1 = fmaxf(v1, 0.f);
            v2 = fmaxf(v2, 0.f); v3 = fmaxf(v3, 0.f);
        }
        if (LSM) {
            // NCG==16: the 16 lanes owning one row form a contiguous shfl subgroup
            float mx = fmaxf(fmaxf(v0, v1), fmaxf(v2, v3));
            #pragma unroll
            for (int m = 1; m < 16; m <<= 1)
                mx = fmaxf(mx, __shfl_xor_sync(0xffffffffu, mx, m));
            float s = expf(v0 - mx) + expf(v1 - mx) + expf(v2 - mx) + expf(v3 - mx);
            #pragma unroll
            for (int m = 1; m < 16; m <<= 1)
                s += __shfl_xor_sync(0xffffffffu, s, m);
            float l = mx + logf(s);
            v0 -= l; v1 -= l; v2 -= l; v3 -= l;
        }
        if (n < N_NODES) {
            float4 o = make_float4(v0, v1, v2, v3);
            *(float4*)&out[(size_t)n * COUT + cg * 4] = o;
        }
    }
}

// ---------------- launch ----------------
extern "C" void kernel_launch(void* const* d_in, const int* in_sizes, int n_in,
                              void* d_out, int out_size) {
    (void)in_sizes; (void)n_in; (void)out_size;
    const float4* x4  = (const float4*)d_in[0];
    const void*   ei  = d_in[1];
    const float* Wl1 = (const float*)d_in[2];
    const float* bl1 = (const float*)d_in[3];
    const float* Wr1 = (const float*)d_in[4];
    const float* Wl2 = (const float*)d_in[5];
    const float* bl2 = (const float*)d_in[6];
    const float* Wr2 = (const float*)d_in[7];
    const float* Wl3 = (const float*)d_in[8];
    const float* bl3 = (const float*)d_in[9];
    const float* Wr3 = (const float*)d_in[10];
    const float* Wl4 = (const float*)d_in[11];
    const float* bl4 = (const float*)d_in[12];
    const float* Wr4 = (const float*)d_in[13];
    float* out = (float*)d_out;

    // dtype detect + CSR build (mean aggregation is order-insensitive up to fp rounding)
    k_detect<<<1, 32>>>((const unsigned int*)ei);
    k_zero_deg<<<(N_NODES + 255) / 256, 256>>>();
    k_count<<<(N_EDGES + 255) / 256, 256>>>(ei);
    k_scan<<<1, 1024>>>();
    k_fill<<<(N_EDGES + 255) / 256, 256>>>(ei);

    const int AGG_GRID = (N_NODES * 32 + 255) / 256;  // one warp per node
    const int G64  = (N_NODES + 63)  / 64;            // BM=64 tiles
    const int G128 = (N_NODES + 127) / 128;           // BM=128 tiles

    // L1: x -> ha, relu                (CIN=128, COUT=128, BM=64)
    k_agg<128,0><<<AGG_GRID, 256>>>(x4);
    k_gemm<128,128,64,true,false,0,1><<<G64, 256>>>(x4, Wl1, bl1, Wr1, nullptr);
    // L2: ha -> hb, relu (model-level relu after sage2)
    k_agg<128,1><<<AGG_GRID, 256>>>(nullptr);
    k_gemm<128,128,64,true,false,1,2><<<G64, 256>>>(nullptr, Wl2, bl2, Wr2, nullptr);
    // L3: hb -> ha, relu               (CIN=128, COUT=64, BM=128)
    k_agg<128,2><<<AGG_GRID, 256>>>(nullptr);
    k_gemm<128,64,128,true,false,2,1><<<G128, 256>>>(nullptr, Wl3, bl3, Wr3, nullptr);
    // L4: ha -> out, log_softmax       (CIN=64, COUT=64, BM=128)
    k_agg<64,1><<<AGG_GRID, 256>>>(nullptr);
    k_gemm<64,64,128,false,true,1,0><<<G128, 256>>>(nullptr, Wl4, bl4, Wr4, out);
}

// round 5
// speedup vs baseline: 1.2255x; 1.2255x over previous
#include <cuda_runtime.h>
#include <math.h>

#define N_NODES 50000
#define N_EDGES 800000
#define NBLK    ((N_NODES + 255) / 256)   // 196 scan blocks

// ---------------- scratch (__device__ globals; float4-typed for alignment) ----------------
__device__ int    g_idx64;                        // 1 if edge_index is int64, 0 if int32
__device__ int    g_deg[N_NODES];
__device__ float  g_invdeg[N_NODES];
__device__ int    g_rowptr[N_NODES + 1];
__device__ int    g_cursor[N_NODES];
__device__ int    g_src[N_EDGES];
__device__ int    g_bsum[256];                    // per-block degree sums (NBLK <= 256)
__device__ int    g_boff[256];                    // exclusive offsets per block
__device__ float4 g_agg4[(size_t)N_NODES * 32];   // up to 128 ch per node
__device__ float4 g_ha4 [(size_t)N_NODES * 32];
__device__ float4 g_hb4 [(size_t)N_NODES * 32];

// ---------------- f32x2 packed helpers ----------------
typedef unsigned long long u64;
__device__ __forceinline__ u64 pack2(float lo, float hi) {
    u64 r; asm("mov.b64 %0, {%1,%2};" : "=l"(r) : "f"(lo), "f"(hi)); return r;
}
__device__ __forceinline__ u64 fma2(u64 a, u64 b, u64 c) {
    u64 d; asm("fma.rn.f32x2 %0, %1, %2, %3;" : "=l"(d) : "l"(a), "l"(b), "l"(c)); return d;
}
__device__ __forceinline__ float2 unpack2(u64 v) {
    float2 f; asm("mov.b64 {%0,%1}, %2;" : "=f"(f.x), "=f"(f.y) : "l"(v)); return f;
}

// ---------------- edge-index dtype detection (warp-parallel, one ballot) ----------------
// int64 edge values are < 50000 -> every odd 32-bit word is 0. Sample 128 odd words.
__global__ void k_detect(const unsigned int* __restrict__ w) {
    int lane = threadIdx.x & 31;
    unsigned int v = w[2 * lane + 1] | w[2 * (lane + 32) + 1] |
                     w[2 * (lane + 64) + 1] | w[2 * (lane + 96) + 1];
    unsigned int any = __ballot_sync(0xffffffffu, v != 0u);
    if (lane == 0) g_idx64 = (any == 0u) ? 1 : 0;
}

__device__ __forceinline__ int clampi(int v, int lo, int hi) {
    return v < lo ? lo : (v > hi ? hi : v);
}
__device__ __forceinline__ int edge_at(const void* ei, long long pos) {
    int v;
    if (g_idx64) v = (int)((const long long*)ei)[pos];
    else         v = ((const int*)ei)[pos];
    return clampi(v, 0, N_NODES - 1);
}

// ---------------- CSR build ----------------
__global__ void k_zero_deg() {
    int i = blockIdx.x * blockDim.x + threadIdx.x;
    if (i < N_NODES) g_deg[i] = 0;
}

__global__ void k_count(const void* __restrict__ ei) {
    int e = blockIdx.x * blockDim.x + threadIdx.x;
    if (e < N_EDGES) {
        int d = edge_at(ei, (long long)N_EDGES + e);
        atomicAdd(&g_deg[d], 1);
    }
}

// phase A: per-256-chunk degree sums
__global__ void k_bsum() {
    __shared__ int sh[256];
    int i = blockIdx.x * 256 + threadIdx.x;
    sh[threadIdx.x] = (i < N_NODES) ? g_deg[i] : 0;
    __syncthreads();
    for (int off = 128; off > 0; off >>= 1) {
        if (threadIdx.x < off) sh[threadIdx.x] += sh[threadIdx.x + off];
        __syncthreads();
    }
    if (threadIdx.x == 0) g_bsum[blockIdx.x] = sh[0];
}

// phase B: scan block sums (single small block)
__global__ void k_bscan() {
    __shared__ int sh[256];
    int t = threadIdx.x;
    int v = (t < NBLK) ? g_bsum[t] : 0;
    sh[t] = v;
    __syncthreads();
    for (int off = 1; off < 256; off <<= 1) {
        int u = (t >= off) ? sh[t - off] : 0;
        __syncthreads();
        sh[t] += u;
        __syncthreads();
    }
    if (t < NBLK) g_boff[t] = sh[t] - v;   // exclusive
    if (t == 0)   g_rowptr[N_NODES] = N_EDGES;
}

// phase C: per-block exclusive scan + scatter rowptr/cursor/invdeg
__global__ void k_scatter() {
    __shared__ int sh[256];
    int t = threadIdx.x;
    int i = blockIdx.x * 256 + t;
    int d = (i < N_NODES) ? g_deg[i] : 0;
    sh[t] = d;
    __syncthreads();
    for (int off = 1; off < 256; off <<= 1) {
        int u = (t >= off) ? sh[t - off] : 0;
        __syncthreads();
        sh[t] += u;
        __syncthreads();
    }
    if (i < N_NODES) {
        int base = g_boff[blockIdx.x] + sh[t] - d;   // exclusive within block + block offset
        g_rowptr[i] = base;
        g_cursor[i] = base;
        g_invdeg[i] = 1.0f / fmaxf((float)d, 1.0f);
    }
}

__global__ void k_fill(const void* __restrict__ ei) {
    int e = blockIdx.x * blockDim.x + threadIdx.x;
    if (e < N_EDGES) {
        int s = edge_at(ei, e);
        int d = edge_at(ei, (long long)N_EDGES + e);
        int pos = atomicAdd(&g_cursor[d], 1);
        pos = clampi(pos, 0, N_EDGES - 1);
        g_src[pos] = s;
    }
}

// ---------------- atomic-free mean aggregation: one warp per node ----------------
// SSEL: 0 = xparam (harness input), 1 = g_ha4, 2 = g_hb4. Output: g_agg4.
template <int C, int SSEL>
__global__ void k_agg(const float4* __restrict__ xparam4) {
    const float4* feat = (SSEL == 0) ? xparam4 : (SSEL == 1) ? (const float4*)g_ha4
                                                             : (const float4*)g_hb4;
    int w    = (blockIdx.x * blockDim.x + threadIdx.x) >> 5;
    int lane = threadIdx.x & 31;
    if (w >= N_NODES) return;
    int beg = g_rowptr[w], end = g_rowptr[w + 1];
    if (C == 128) {
        float4 a = make_float4(0.f, 0.f, 0.f, 0.f);
        int e = beg;
        for (; e + 1 < end; e += 2) {
            int s0 = g_src[e];
            int s1 = g_src[e + 1];
            float4 v0 = feat[(size_t)s0 * 32 + lane];
            float4 v1 = feat[(size_t)s1 * 32 + lane];
            a.x += v0.x; a.y += v0.y; a.z += v0.z; a.w += v0.w;
            a.x += v1.x; a.y += v1.y; a.z += v1.z; a.w += v1.w;
        }
        if (e < end) {
            int s0 = g_src[e];
            float4 v0 = feat[(size_t)s0 * 32 + lane];
            a.x += v0.x; a.y += v0.y; a.z += v0.z; a.w += v0.w;
        }
        float iv = g_invdeg[w];
        a.x *= iv; a.y *= iv; a.z *= iv; a.w *= iv;
        g_agg4[(size_t)w * 32 + lane] = a;
    } else { // C == 64 : rows are 32 float2 wide
        const float2* f2 = (const float2*)feat;
        float2 a = make_float2(0.f, 0.f);
        int e = beg;
        for (; e + 1 < end; e += 2) {
            int s0 = g_src[e];
            int s1 = g_src[e + 1];
            float2 v0 = f2[(size_t)s0 * 32 + lane];
            float2 v1 = f2[(size_t)s1 * 32 + lane];
            a.x += v0.x; a.y += v0.y;
            a.x += v1.x; a.y += v1.y;
        }
        if (e < end) {
            int s0 = g_src[e];
            float2 v0 = f2[(size_t)s0 * 32 + lane];
            a.x += v0.x; a.y += v0.y;
        }
        float iv = g_invdeg[w];
        a.x *= iv; a.y *= iv;
        ((float2*)g_agg4)[(size_t)w * 32 + lane] = a;
    }
}

// ---------------- fused SAGE GEMM (f32x2 core): out = mean@Wl^T + bl + x@Wr^T ---------------
// 256 threads/block, one BM-node tile per block, K processed in KC=16 chunks.
// Static shared only. Thread owns R=8 rows x 4 output channels (2 packed f32x2 accs each).
// XSEL: 0 = xparam, 1 = g_ha4, 2 = g_hb4.   OSEL: 0 = outparam, 1 = g_ha4, 2 = g_hb4.
template <int CIN, int COUT, int BM, bool RELU, bool LSM, int XSEL, int OSEL>
__launch_bounds__(256, 1)
__global__ void k_gemm(const float4* __restrict__ xparam4,
                       const float* __restrict__ Wl, const float* __restrict__ bl,
                       const float* __restrict__ Wr, float* __restrict__ outparam) {
    constexpr int KC    = 16;                 // K-chunk (floats)
    constexpr int KQ    = KC / 4;             // K-chunk in float4
    constexpr int NCG   = COUT / 4;           // channel groups
    constexpr int NGR   = 256 / NCG;          // node groups
    constexpr int R     = BM / NGR;           // rows per thread (== 8)
    constexpr int COUTP = COUT + 4;           // pad (rows stay 16B-aligned)
    constexpr int C4    = CIN / 4;

    __shared__ float Wl_s[KC][COUTP];
    __shared__ float Wr_s[KC][COUTP];
    __shared__ float vm_s[BM][KC];
    __shared__ float vx_s[BM][KC];

    const float4* xin4  = (XSEL == 0) ? xparam4 : (XSEL == 1) ? (const float4*)g_ha4
                                                              : (const float4*)g_hb4;
    const float4* mean4 = (const float4*)g_agg4;
    float*        out   = (OSEL == 0) ? outparam : (OSEL == 1) ? (float*)g_ha4
                                                               : (float*)g_hb4;

    const int tid = threadIdx.x;
    const int cg  = tid % NCG;
    const int ng  = tid / NCG;
    const int nb  = blockIdx.x * BM;

    u64 acc[R][2];
    {
        const u64 b0 = ((const u64*)bl)[cg * 2];
        const u64 b1 = ((const u64*)bl)[cg * 2 + 1];
        #pragma unroll
        for (int r = 0; r < R; r++) { acc[r][0] = b0; acc[r][1] = b1; }
    }

    for (int kb4 = 0; kb4 < C4; kb4 += KQ) {
        __syncthreads();
        // stage weight K-panels: Wl/Wr are [co][ci] row-major; smem is [k][co]
        for (int idx = tid; idx < KC * COUT; idx += 256) {
            int co = idx / KC;
            int k  = idx % KC;
            Wl_s[k][co] = Wl[co * CIN + kb4 * 4 + k];
            Wr_s[k][co] = Wr[co * CIN + kb4 * 4 + k];
        }
        // stage value tiles (float4 stores into scalar-layout smem; rows are 64B, aligned)
        for (int idx = tid; idx < BM * KQ; idx += 256) {
            int nl = idx / KQ;
            int q  = idx % KQ;
            int n  = nb + nl; if (n >= N_NODES) n = N_NODES - 1;
            *(float4*)&vm_s[nl][q * 4] = mean4[(size_t)n * C4 + kb4 + q];
            *(float4*)&vx_s[nl][q * 4] = xin4 [(size_t)n * C4 + kb4 + q];
        }
        __syncthreads();

        #pragma unroll
        for (int k = 0; k < KC; k++) {
            const u64 wl0 = *(const u64*)&Wl_s[k][cg * 4];
            const u64 wl1 = *(const u64*)&Wl_s[k][cg * 4 + 2];
            const u64 wr0 = *(const u64*)&Wr_s[k][cg * 4];
            const u64 wr1 = *(const u64*)&Wr_s[k][cg * 4 + 2];
            #pragma unroll
            for (int r = 0; r < R; r++) {
                float mv = vm_s[ng * R + r][k];
                float xv = vx_s[ng * R + r][k];
                u64 m2 = pack2(mv, mv);
                u64 x2 = pack2(xv, xv);
                acc[r][0] = fma2(m2, wl0, acc[r][0]);
                acc[r][1] = fma2(m2, wl1, acc[r][1]);
                acc[r][0] = fma2(x2, wr0, acc[r][0]);
                acc[r][1] = fma2(x2, wr1, acc[r][1]);
            }
        }
    }

    // epilogue
    #pragma unroll
    for (int r = 0; r < R; r++) {
        int n = nb + ng * R + r;
        float2 a = unpack2(acc[r][0]);
        float2 b = unpack2(acc[r][1]);
        float v0 = a.x, v1 = a.y, v2 = b.x, v3 = b.y;
        if (RELU) {
            v0 = fmaxf(v0, 0.f); v1 = fmaxf(v1, 0.f);
            v2 = fmaxf(v2, 0.f); v3 = fmaxf(v3, 0.f);
        }
        if (LSM) {
            // NCG==16: the 16 lanes owning one row form a contiguous shfl subgroup
            float mx = fmaxf(fmaxf(v0, v1), fmaxf(v2, v3));
            #pragma unroll
            for (int m = 1; m < 16; m <<= 1)
                mx = fmaxf(mx, __shfl_xor_sync(0xffffffffu, mx, m));
            float s = expf(v0 - mx) + expf(v1 - mx) + expf(v2 - mx) + expf(v3 - mx);
            #pragma unroll
            for (int m = 1; m < 16; m <<= 1)
                s += __shfl_xor_sync(0xffffffffu, s, m);
            float l = mx + logf(s);
            v0 -= l; v1 -= l; v2 -= l; v3 -= l;
        }
        if (n < N_NODES) {
            float4 o = make_float4(v0, v1, v2, v3);
            *(float4*)&out[(size_t)n * COUT + cg * 4] = o;
        }
    }
}

// ---------------- launch ----------------
extern "C" void kernel_launch(void* const* d_in, const int* in_sizes, int n_in,
                              void* d_out, int out_size) {
    (void)in_sizes; (void)n_in; (void)out_size;
    const float4* x4  = (const float4*)d_in[0];
    const void*   ei  = d_in[1];
    const float* Wl1 = (const float*)d_in[2];
    const float* bl1 = (const float*)d_in[3];
    const float* Wr1 = (const float*)d_in[4];
    const float* Wl2 = (const float*)d_in[5];
    const float* bl2 = (const float*)d_in[6];
    const float* Wr2 = (const float*)d_in[7];
    const float* Wl3 = (const float*)d_in[8];
    const float* bl3 = (const float*)d_in[9];
    const float* Wr3 = (const float*)d_in[10];
    const float* Wl4 = (const float*)d_in[11];
    const float* bl4 = (const float*)d_in[12];
    const float* Wr4 = (const float*)d_in[13];
    float* out = (float*)d_out;

    // dtype detect + CSR build (parallel scan)
    k_detect<<<1, 32>>>((const unsigned int*)ei);
    k_zero_deg<<<NBLK, 256>>>();
    k_count<<<(N_EDGES + 255) / 256, 256>>>(ei);
    k_bsum<<<NBLK, 256>>>();
    k_bscan<<<1, 256>>>();
    k_scatter<<<NBLK, 256>>>();
    k_fill<<<(N_EDGES + 255) / 256, 256>>>(ei);

    const int AGG_GRID = (N_NODES * 32 + 255) / 256;  // one warp per node
    const int G64  = (N_NODES + 63)  / 64;            // BM=64 tiles
    const int G128 = (N_NODES + 127) / 128;           // BM=128 tiles

    // L1: x -> ha, relu                (CIN=128, COUT=128, BM=64)
    k_agg<128,0><<<AGG_GRID, 256>>>(x4);
    k_gemm<128,128,64,true,false,0,1><<<G64, 256>>>(x4, Wl1, bl1, Wr1, nullptr);
    // L2: ha -> hb, relu (model-level relu after sage2)
    k_agg<128,1><<<AGG_GRID, 256>>>(nullptr);
    k_gemm<128,128,64,true,false,1,2><<<G64, 256>>>(nullptr, Wl2, bl2, Wr2, nullptr);
    // L3: hb -> ha, relu               (CIN=128, COUT=64, BM=128)
    k_agg<128,2><<<AGG_GRID, 256>>>(nullptr);
    k_gemm<128,64,128,true,false,2,1><<<G128, 256>>>(nullptr, Wl3, bl3, Wr3, nullptr);
    // L4: ha -> out, log_softmax       (CIN=64, COUT=64, BM=128)
    k_agg<64,1><<<AGG_GRID, 256>>>(nullptr);
    k_gemm<64,64,128,false,true,1,0><<<G128, 256>>>(nullptr, Wl4, bl4, Wr4, out);
}